// round 3
// baseline (speedup 1.0000x reference)
#include <cuda_runtime.h>
#include <math.h>

#define BATCH   2
#define QN      900
#define BQ      (BATCH*QN)      // 1800
#define CDIM    256
#define VNUM    6
#define KKP     4
#define NSAMP   (VNUM*KKP)      // 24
#define NHEADS  8
#define HDIM    32

// scratch (no allocations allowed)
__device__ float g_ctx[BQ*CDIM];
__device__ float g_qp [BQ*CDIM];
__device__ float g_kp [BQ*CDIM];
__device__ float g_vp [BQ*CDIM];
__device__ float g_o  [BQ*CDIM];

// ---------------------------------------------------------------------------
// Kernel 1: project + bilinear-gather the multi-view context  -> g_ctx[B,Q,C]
// One block per (b,q); 256 threads (one per channel).
// ---------------------------------------------------------------------------
__global__ __launch_bounds__(256) void sampler_kernel(
                               const float* __restrict__ f0,
                               const float* __restrict__ f1,
                               const float* __restrict__ refs,
                               const float* __restrict__ intr,
                               const float* __restrict__ extr)
{
    int bq = blockIdx.x;            // 0..1799
    int b  = bq / QN;
    int tid = threadIdx.x;

    __shared__ float s_w[2*NSAMP][4];
    __shared__ int   s_off[2*NSAMP][4];
    __shared__ int   s_valid[2*NSAMP];
    __shared__ int   s_cnt[2];
    __shared__ float s_ref[3];

    if (tid < 2) s_cnt[tid] = 0;
    if (tid < 3) s_ref[tid] = refs[(size_t)bq*3 + tid];
    __syncthreads();

    if (tid < 2*NSAMP) {
        int lvl = tid / NSAMP;
        int i   = tid % NSAMP;
        int v   = i / KKP, k = i % KKP;
        const float kx[4] = {0.f, 2.f, 0.f, -2.f};
        const float ky[4] = {0.f, 0.f, 2.f, 0.f};
        float rx = s_ref[0] + kx[k];
        float ry = s_ref[1] + ky[k];
        float rz = s_ref[2];
        const float* E  = extr + (size_t)(b*VNUM + v)*16;
        float cx = E[0]*rx + E[1]*ry + E[2]*rz  + E[3];
        float cy = E[4]*rx + E[5]*ry + E[6]*rz  + E[7];
        float cz = E[8]*rx + E[9]*ry + E[10]*rz + E[11];
        const float* Km = intr + (size_t)(b*VNUM + v)*9;
        float u  = Km[0]*cx + Km[1]*cy + Km[2]*cz;
        float vv = Km[3]*cx + Km[4]*cy + Km[5]*cz;
        float z  = Km[6]*cx + Km[7]*cy + Km[8]*cz;

        int W = lvl ? 88 : 176;
        int H = lvl ? 32 : 64;
        float zs = (fabsf(z) > 1e-6f) ? z : 1e-6f;
        // grid normalize + align_corners un-normalize cancel: pixel coord = u/zs
        float x = u / zs, y = vv / zs;
        int valid = (z > 0.f) ? 1 : 0;
        s_valid[tid] = valid;
        if (valid) atomicAdd(&s_cnt[lvl], 1);

        float x0 = floorf(x), y0 = floorf(y);
        float wx1 = x - x0, wx0 = 1.f - wx1;
        float wy1 = y - y0, wy0 = 1.f - wy1;
        float xs[2]  = {x0, x0 + 1.f};
        float ys[2]  = {y0, y0 + 1.f};
        float wxs[2] = {wx0, wx1};
        float wys[2] = {wy0, wy1};
        #pragma unroll
        for (int t = 0; t < 4; t++) {
            float xi = xs[t & 1], yi = ys[t >> 1];
            bool inb = (xi >= 0.f) && (xi <= (float)(W - 1)) &&
                       (yi >= 0.f) && (yi <= (float)(H - 1));
            s_w[tid][t]   = wxs[t & 1] * wys[t >> 1];
            s_off[tid][t] = inb ? ((int)yi * W + (int)xi) : -1;
        }
    }
    __syncthreads();

    float invc0 = 1.f / fmaxf((float)s_cnt[0], 1.f);
    float invc1 = 1.f / fmaxf((float)s_cnt[1], 1.f);

    int c = tid;  // channel
    float total = 0.f;
    #pragma unroll
    for (int lvl = 0; lvl < 2; lvl++) {
        const float* f = lvl ? f1 : f0;
        int HW = lvl ? (32*88) : (64*176);
        float s = 0.f;
        for (int i = 0; i < NSAMP; i++) {
            int idx = lvl*NSAMP + i;
            if (!s_valid[idx]) continue;
            int v = i / KKP;
            size_t base = ((size_t)(b*VNUM + v)*CDIM + c) * (size_t)HW;
            #pragma unroll
            for (int t = 0; t < 4; t++) {
                int off = s_off[idx][t];
                if (off >= 0) s += s_w[idx][t] * __ldg(&f[base + off]);
            }
        }
        total += s * (lvl ? invc1 : invc0);
    }
    g_ctx[(size_t)bq*CDIM + c] = 0.5f * total;
}

// ---------------------------------------------------------------------------
// SGEMM: C[M,256] = A[M,256] @ W^T (W is [256,256] row-major) + bias
// 64x64 tile, BK=16, 256 threads, 4x4 register tile per thread.
// ---------------------------------------------------------------------------
__device__ __forceinline__ void sgemm_64x64(const float* __restrict__ A,
                                            const float* __restrict__ W,
                                            const float* __restrict__ bias,
                                            float* __restrict__ C,
                                            int M, int m0, int n0)
{
    __shared__ float As[16][64];
    __shared__ float Bs[16][64];
    int tid = threadIdx.x;
    int tx = tid & 15, ty = tid >> 4;
    float acc[4][4] = {};

    for (int k0 = 0; k0 < 256; k0 += 16) {
        #pragma unroll
        for (int r = 0; r < 4; r++) {
            int idx = tid + r*256;           // 0..1023
            int m = idx >> 4, kk = idx & 15;
            int gm = m0 + m;
            float val = (gm < M) ? A[(size_t)gm*256 + k0 + kk] : 0.f;
            As[kk][m] = val;
        }
        #pragma unroll
        for (int r = 0; r < 4; r++) {
            int idx = tid + r*256;
            int n = idx >> 4, kk = idx & 15;
            Bs[kk][n] = W[(size_t)(n0 + n)*256 + k0 + kk];
        }
        __syncthreads();
        #pragma unroll
        for (int kk = 0; kk < 16; kk++) {
            float a[4], bb[4];
            #pragma unroll
            for (int i = 0; i < 4; i++) a[i]  = As[kk][ty*4 + i];
            #pragma unroll
            for (int j = 0; j < 4; j++) bb[j] = Bs[kk][tx*4 + j];
            #pragma unroll
            for (int i = 0; i < 4; i++)
                #pragma unroll
                for (int j = 0; j < 4; j++)
                    acc[i][j] += a[i]*bb[j];
        }
        __syncthreads();
    }
    #pragma unroll
    for (int i = 0; i < 4; i++) {
        int gm = m0 + ty*4 + i;
        if (gm >= M) continue;
        #pragma unroll
        for (int j = 0; j < 4; j++) {
            int gn = n0 + tx*4 + j;
            C[(size_t)gm*256 + gn] = acc[i][j] + bias[gn];
        }
    }
}

__global__ __launch_bounds__(256) void gemm_qkv_kernel(
                                const float* __restrict__ queries,
                                const float* __restrict__ Wq, const float* __restrict__ bq,
                                const float* __restrict__ Wk, const float* __restrict__ bk,
                                const float* __restrict__ Wv, const float* __restrict__ bv)
{
    const float* A; const float* W; const float* bias; float* C;
    if (blockIdx.z == 0)      { A = queries; W = Wq; bias = bq; C = g_qp; }
    else if (blockIdx.z == 1) { A = g_ctx;   W = Wk; bias = bk; C = g_kp; }
    else                      { A = g_ctx;   W = Wv; bias = bv; C = g_vp; }
    sgemm_64x64(A, W, bias, C, BQ, blockIdx.x*64, blockIdx.y*64);
}

__global__ __launch_bounds__(256) void gemm_out_kernel(
                                const float* __restrict__ Wo,
                                const float* __restrict__ bo,
                                float* __restrict__ out)
{
    sgemm_64x64(g_o, Wo, bo, out, BQ, blockIdx.x*64, blockIdx.y*64);
}

// ---------------------------------------------------------------------------
// Kernel 3: flash-style attention. grid (qtile, head, batch); 128 thr,
// 1 query per thread, K/V staged in 64-row smem chunks (broadcast reads).
// ---------------------------------------------------------------------------
#define KCH 64
__global__ __launch_bounds__(128) void attn_kernel()
{
    int qt = blockIdx.x, h = blockIdx.y, b = blockIdx.z;
    int tid = threadIdx.x;
    int qi = qt*128 + tid;
    bool active = qi < QN;

    __shared__ float Ks[KCH][32];
    __shared__ float Vs[KCH][32];

    const float scale = 0.17677669529663687f;  // 1/sqrt(32)
    float qreg[HDIM];
    if (active) {
        const float* qp = g_qp + ((size_t)(b*QN + qi))*CDIM + h*HDIM;
        #pragma unroll
        for (int d = 0; d < HDIM; d += 4) {
            float4 t = *reinterpret_cast<const float4*>(qp + d);
            qreg[d] = t.x*scale; qreg[d+1] = t.y*scale;
            qreg[d+2] = t.z*scale; qreg[d+3] = t.w*scale;
        }
    } else {
        #pragma unroll
        for (int d = 0; d < HDIM; d++) qreg[d] = 0.f;
    }

    float m = -1e30f, l = 0.f;
    float acc[HDIM];
    #pragma unroll
    for (int d = 0; d < HDIM; d++) acc[d] = 0.f;

    for (int kk = 0; kk < QN; kk += KCH) {
        int jn = QN - kk; if (jn > KCH) jn = KCH;
        // cooperative load of K,V chunk: KCH rows x 32 cols.
        // 128 threads, each thread loads two float4 pairs per half-chunk.
        {
            int j  = tid >> 1;           // 0..63
            int cb = (tid & 1) * 16;     // 16-float segment
            int row = kk + j;
            if (row < QN) {
                const float* kp = g_kp + ((size_t)(b*QN + row))*CDIM + h*HDIM + cb;
                const float* vp = g_vp + ((size_t)(b*QN + row))*CDIM + h*HDIM + cb;
                #pragma unroll
                for (int u = 0; u < 16; u += 4) {
                    *reinterpret_cast<float4*>(&Ks[j][cb + u]) =
                        *reinterpret_cast<const float4*>(kp + u);
                    *reinterpret_cast<float4*>(&Vs[j][cb + u]) =
                        *reinterpret_cast<const float4*>(vp + u);
                }
            } else {
                float4 zz = make_float4(0.f, 0.f, 0.f, 0.f);
                #pragma unroll
                for (int u = 0; u < 16; u += 4) {
                    *reinterpret_cast<float4*>(&Ks[j][cb + u]) = zz;
                    *reinterpret_cast<float4*>(&Vs[j][cb + u]) = zz;
                }
            }
        }
        __syncthreads();

        float s[KCH];
        #pragma unroll
        for (int j = 0; j < KCH; j++) s[j] = 0.f;
        #pragma unroll
        for (int d = 0; d < HDIM; d++) {
            float qd = qreg[d];
            #pragma unroll
            for (int j = 0; j < KCH; j++) s[j] += qd * Ks[j][d];
        }
        if (jn < KCH) {
            for (int j = jn; j < KCH; j++) s[j] = -1e30f;
        }
        float mnew = m;
        #pragma unroll
        for (int j = 0; j < KCH; j++) mnew = fmaxf(mnew, s[j]);
        float corr = __expf(m - mnew);
        l *= corr;
        #pragma unroll
        for (int d = 0; d < HDIM; d++) acc[d] *= corr;
        #pragma unroll
        for (int j = 0; j < KCH; j++) {
            float p = __expf(s[j] - mnew);
            l += p;
            #pragma unroll
            for (int d = 0; d < HDIM; d++) acc[d] += p * Vs[j][d];
        }
        m = mnew;
        __syncthreads();
    }

    if (active) {
        float invl = 1.f / l;
        float* o = g_o + ((size_t)(b*QN + qi))*CDIM + h*HDIM;
        #pragma unroll
        for (int d = 0; d < HDIM; d += 4) {
            float4 t;
            t.x = acc[d]   * invl; t.y = acc[d+1] * invl;
            t.z = acc[d+2] * invl; t.w = acc[d+3] * invl;
            *reinterpret_cast<float4*>(o + d) = t;
        }
    }
}

// ---------------------------------------------------------------------------
extern "C" void kernel_launch(void* const* d_in, const int* in_sizes, int n_in,
                              void* d_out, int out_size)
{
    const float* f0      = (const float*)d_in[0];
    const float* f1      = (const float*)d_in[1];
    const float* refs    = (const float*)d_in[2];
    const float* intr    = (const float*)d_in[3];
    const float* extr    = (const float*)d_in[4];
    const float* queries = (const float*)d_in[5];
    const float* Wq = (const float*)d_in[6];  const float* bq = (const float*)d_in[7];
    const float* Wk = (const float*)d_in[8];  const float* bk = (const float*)d_in[9];
    const float* Wv = (const float*)d_in[10]; const float* bv = (const float*)d_in[11];
    const float* Wo = (const float*)d_in[12]; const float* bo = (const float*)d_in[13];
    float* out = (float*)d_out;

    sampler_kernel<<<BQ, 256>>>(f0, f1, refs, intr, extr);
    gemm_qkv_kernel<<<dim3(29, 4, 3), 256>>>(queries, Wq, bq, Wk, bk, Wv, bv);
    attn_kernel<<<dim3(8, NHEADS, BATCH), 128>>>();
    gemm_out_kernel<<<dim3(29, 4, 1), 256>>>(Wo, bo, out);
}

// round 4
// speedup vs baseline: 1.1305x; 1.1305x over previous
#include <cuda_runtime.h>
#include <math.h>
#include <stdint.h>

#define BATCH   2
#define QN      900
#define BQ      (BATCH*QN)      // 1800
#define CDIM    256
#define VNUM    6
#define KKP     4
#define NSAMP   (VNUM*KKP)      // 24
#define NHEADS  8
#define HDIM    32

// scratch (no allocations allowed)
__device__ float g_ctx[BQ*CDIM];
__device__ float g_qp [BQ*CDIM];
__device__ float g_kp [BQ*CDIM];
__device__ float g_vp [BQ*CDIM];
__device__ float g_o  [BQ*CDIM];

// ---------------------------------------------------------------------------
// Kernel 1: project + bilinear-gather the multi-view context  -> g_ctx[B,Q,C]
// ---------------------------------------------------------------------------
__global__ __launch_bounds__(256) void sampler_kernel(
                               const float* __restrict__ f0,
                               const float* __restrict__ f1,
                               const float* __restrict__ refs,
                               const float* __restrict__ intr,
                               const float* __restrict__ extr)
{
    int bq = blockIdx.x;            // 0..1799
    int b  = bq / QN;
    int tid = threadIdx.x;

    __shared__ float s_w[2*NSAMP][4];
    __shared__ int   s_off[2*NSAMP][4];
    __shared__ int   s_valid[2*NSAMP];
    __shared__ int   s_cnt[2];
    __shared__ float s_ref[3];

    if (tid < 2) s_cnt[tid] = 0;
    if (tid < 3) s_ref[tid] = refs[(size_t)bq*3 + tid];
    __syncthreads();

    if (tid < 2*NSAMP) {
        int lvl = tid / NSAMP;
        int i   = tid % NSAMP;
        int v   = i / KKP, k = i % KKP;
        const float kx[4] = {0.f, 2.f, 0.f, -2.f};
        const float ky[4] = {0.f, 0.f, 2.f, 0.f};
        float rx = s_ref[0] + kx[k];
        float ry = s_ref[1] + ky[k];
        float rz = s_ref[2];
        const float* E  = extr + (size_t)(b*VNUM + v)*16;
        float cx = E[0]*rx + E[1]*ry + E[2]*rz  + E[3];
        float cy = E[4]*rx + E[5]*ry + E[6]*rz  + E[7];
        float cz = E[8]*rx + E[9]*ry + E[10]*rz + E[11];
        const float* Km = intr + (size_t)(b*VNUM + v)*9;
        float u  = Km[0]*cx + Km[1]*cy + Km[2]*cz;
        float vv = Km[3]*cx + Km[4]*cy + Km[5]*cz;
        float z  = Km[6]*cx + Km[7]*cy + Km[8]*cz;

        int W = lvl ? 88 : 176;
        int H = lvl ? 32 : 64;
        float zs = (fabsf(z) > 1e-6f) ? z : 1e-6f;
        float x = u / zs, y = vv / zs;   // grid-normalize cancels
        int valid = (z > 0.f) ? 1 : 0;
        s_valid[tid] = valid;
        if (valid) atomicAdd(&s_cnt[lvl], 1);

        float x0 = floorf(x), y0 = floorf(y);
        float wx1 = x - x0, wx0 = 1.f - wx1;
        float wy1 = y - y0, wy0 = 1.f - wy1;
        float xs[2]  = {x0, x0 + 1.f};
        float ys[2]  = {y0, y0 + 1.f};
        float wxs[2] = {wx0, wx1};
        float wys[2] = {wy0, wy1};
        #pragma unroll
        for (int t = 0; t < 4; t++) {
            float xi = xs[t & 1], yi = ys[t >> 1];
            bool inb = (xi >= 0.f) && (xi <= (float)(W - 1)) &&
                       (yi >= 0.f) && (yi <= (float)(H - 1));
            s_w[tid][t]   = wxs[t & 1] * wys[t >> 1];
            s_off[tid][t] = inb ? ((int)yi * W + (int)xi) : -1;
        }
    }
    __syncthreads();

    float invc0 = 1.f / fmaxf((float)s_cnt[0], 1.f);
    float invc1 = 1.f / fmaxf((float)s_cnt[1], 1.f);

    int c = tid;
    float total = 0.f;
    #pragma unroll
    for (int lvl = 0; lvl < 2; lvl++) {
        const float* f = lvl ? f1 : f0;
        int HW = lvl ? (32*88) : (64*176);
        float s = 0.f;
        for (int i = 0; i < NSAMP; i++) {
            int idx = lvl*NSAMP + i;
            if (!s_valid[idx]) continue;
            int v = i / KKP;
            size_t base = ((size_t)(b*VNUM + v)*CDIM + c) * (size_t)HW;
            #pragma unroll
            for (int t = 0; t < 4; t++) {
                int off = s_off[idx][t];
                if (off >= 0) s += s_w[idx][t] * __ldg(&f[base + off]);
            }
        }
        total += s * (lvl ? invc1 : invc0);
    }
    g_ctx[(size_t)bq*CDIM + c] = 0.5f * total;
}

// ---------------------------------------------------------------------------
// 3xTF32 tensor-core GEMM: C[M,256] = A[M,256] @ W^T + bias
// CTA tile 64x64, 4 warps (2x2), warp tile 32x32, BK=32, single-buffered.
// Accuracy: A,B split hi/lo tf32; D = Ah*Bh + Al*Bh + Ah*Bl  (~fp32 accurate)
// ---------------------------------------------------------------------------
__device__ __forceinline__ uint32_t f2tf32(float f) {
    uint32_t u;
    asm("cvt.rna.tf32.f32 %0, %1;" : "=r"(u) : "f"(f));
    return u;
}

__device__ __forceinline__ void mma_tf32(float* d, const uint32_t* a, const uint32_t* b) {
    asm volatile(
        "mma.sync.aligned.m16n8k8.row.col.f32.tf32.tf32.f32 "
        "{%0,%1,%2,%3}, {%4,%5,%6,%7}, {%8,%9}, {%0,%1,%2,%3};\n"
        : "+f"(d[0]), "+f"(d[1]), "+f"(d[2]), "+f"(d[3])
        : "r"(a[0]), "r"(a[1]), "r"(a[2]), "r"(a[3]), "r"(b[0]), "r"(b[1]));
}

#define KS 36   // smem k-stride (words): conflict-free fragment loads

__device__ __forceinline__ void tc_gemm_64x64(const float* __restrict__ A,
                                              const float* __restrict__ W,
                                              const float* __restrict__ bias,
                                              float* __restrict__ C,
                                              int M, int m0, int n0)
{
    __shared__ uint32_t Ah[64*KS], Al[64*KS], Bh[64*KS], Bl[64*KS];

    int tid  = threadIdx.x;
    int wid  = tid >> 5;
    int lane = tid & 31;
    int g  = lane >> 2;      // group id 0..7
    int tg = lane & 3;       // thread in group 0..3
    int wm = (wid & 1) * 32; // warp m offset
    int wn = (wid >> 1) * 32;// warp n offset

    // loader mapping: 64 rows x 32 cols per matrix, 128 threads x 16 floats
    int lr = tid >> 1;             // row 0..63
    int lc = (tid & 1) * 16;       // col base 0 or 16

    bool arv = (m0 + lr) < M;
    const float* arow = A + (size_t)(m0 + lr) * 256;
    const float* brow = W + (size_t)(n0 + lr) * 256;

    float acc[2][4][4];
    #pragma unroll
    for (int mt = 0; mt < 2; mt++)
        #pragma unroll
        for (int nt = 0; nt < 4; nt++)
            #pragma unroll
            for (int e = 0; e < 4; e++) acc[mt][nt][e] = 0.f;

    for (int k0 = 0; k0 < 256; k0 += 32) {
        // ---- stage tiles to smem with hi/lo tf32 split ----
        #pragma unroll
        for (int u = 0; u < 16; u += 4) {
            float4 va = arv ? *reinterpret_cast<const float4*>(arow + k0 + lc + u)
                            : make_float4(0.f, 0.f, 0.f, 0.f);
            float4 vb = *reinterpret_cast<const float4*>(brow + k0 + lc + u);
            float fa[4] = {va.x, va.y, va.z, va.w};
            float fb[4] = {vb.x, vb.y, vb.z, vb.w};
            #pragma unroll
            for (int e = 0; e < 4; e++) {
                uint32_t h = f2tf32(fa[e]);
                Ah[lr*KS + lc + u + e] = h;
                Al[lr*KS + lc + u + e] = f2tf32(fa[e] - __uint_as_float(h));
                h = f2tf32(fb[e]);
                Bh[lr*KS + lc + u + e] = h;
                Bl[lr*KS + lc + u + e] = f2tf32(fb[e] - __uint_as_float(h));
            }
        }
        __syncthreads();

        #pragma unroll
        for (int k8 = 0; k8 < 4; k8++) {
            int kb = k8 * 8;
            uint32_t ah[2][4], al[2][4], bh[4][2], bl[4][2];
            #pragma unroll
            for (int mt = 0; mt < 2; mt++) {
                int r0 = wm + mt*16 + g;
                ah[mt][0] = Ah[(r0    )*KS + kb + tg];
                ah[mt][1] = Ah[(r0 + 8)*KS + kb + tg];
                ah[mt][2] = Ah[(r0    )*KS + kb + tg + 4];
                ah[mt][3] = Ah[(r0 + 8)*KS + kb + tg + 4];
                al[mt][0] = Al[(r0    )*KS + kb + tg];
                al[mt][1] = Al[(r0 + 8)*KS + kb + tg];
                al[mt][2] = Al[(r0    )*KS + kb + tg + 4];
                al[mt][3] = Al[(r0 + 8)*KS + kb + tg + 4];
            }
            #pragma unroll
            for (int nt = 0; nt < 4; nt++) {
                int n = wn + nt*8 + g;
                bh[nt][0] = Bh[n*KS + kb + tg];
                bh[nt][1] = Bh[n*KS + kb + tg + 4];
                bl[nt][0] = Bl[n*KS + kb + tg];
                bl[nt][1] = Bl[n*KS + kb + tg + 4];
            }
            #pragma unroll
            for (int mt = 0; mt < 2; mt++)
                #pragma unroll
                for (int nt = 0; nt < 4; nt++) {
                    mma_tf32(acc[mt][nt], ah[mt], bh[nt]);
                    mma_tf32(acc[mt][nt], al[mt], bh[nt]);
                    mma_tf32(acc[mt][nt], ah[mt], bl[nt]);
                }
        }
        __syncthreads();
    }

    // ---- epilogue ----
    #pragma unroll
    for (int mt = 0; mt < 2; mt++) {
        #pragma unroll
        for (int nt = 0; nt < 4; nt++) {
            int rm = m0 + wm + mt*16 + g;
            int cn = n0 + wn + nt*8 + tg*2;
            float b0 = bias[cn], b1 = bias[cn + 1];
            if (rm < M) {
                C[(size_t)rm*256 + cn    ] = acc[mt][nt][0] + b0;
                C[(size_t)rm*256 + cn + 1] = acc[mt][nt][1] + b1;
            }
            if (rm + 8 < M) {
                C[(size_t)(rm+8)*256 + cn    ] = acc[mt][nt][2] + b0;
                C[(size_t)(rm+8)*256 + cn + 1] = acc[mt][nt][3] + b1;
            }
        }
    }
}

__global__ __launch_bounds__(128) void gemm_qkv_kernel(
                                const float* __restrict__ queries,
                                const float* __restrict__ Wq, const float* __restrict__ bq,
                                const float* __restrict__ Wk, const float* __restrict__ bk,
                                const float* __restrict__ Wv, const float* __restrict__ bv)
{
    const float* A; const float* W; const float* bias; float* C;
    if (blockIdx.z == 0)      { A = queries; W = Wq; bias = bq; C = g_qp; }
    else if (blockIdx.z == 1) { A = g_ctx;   W = Wk; bias = bk; C = g_kp; }
    else                      { A = g_ctx;   W = Wv; bias = bv; C = g_vp; }
    tc_gemm_64x64(A, W, bias, C, BQ, blockIdx.x*64, blockIdx.y*64);
}

__global__ __launch_bounds__(128) void gemm_out_kernel(
                                const float* __restrict__ Wo,
                                const float* __restrict__ bo,
                                float* __restrict__ out)
{
    tc_gemm_64x64(g_o, Wo, bo, out, BQ, blockIdx.x*64, blockIdx.y*64);
}

// ---------------------------------------------------------------------------
// Kernel 3: flash-style attention. 1 query/thread, 64-row K/V smem chunks.
// ---------------------------------------------------------------------------
#define KCH 64
__global__ __launch_bounds__(128) void attn_kernel()
{
    int qt = blockIdx.x, h = blockIdx.y, b = blockIdx.z;
    int tid = threadIdx.x;
    int qi = qt*128 + tid;
    bool active = qi < QN;

    __shared__ float Ks[KCH][32];
    __shared__ float Vs[KCH][32];

    const float scale = 0.17677669529663687f;  // 1/sqrt(32)
    float qreg[HDIM];
    if (active) {
        const float* qp = g_qp + ((size_t)(b*QN + qi))*CDIM + h*HDIM;
        #pragma unroll
        for (int d = 0; d < HDIM; d += 4) {
            float4 t = *reinterpret_cast<const float4*>(qp + d);
            qreg[d] = t.x*scale; qreg[d+1] = t.y*scale;
            qreg[d+2] = t.z*scale; qreg[d+3] = t.w*scale;
        }
    } else {
        #pragma unroll
        for (int d = 0; d < HDIM; d++) qreg[d] = 0.f;
    }

    float m = -1e30f, l = 0.f;
    float acc[HDIM];
    #pragma unroll
    for (int d = 0; d < HDIM; d++) acc[d] = 0.f;

    for (int kk = 0; kk < QN; kk += KCH) {
        int jn = QN - kk; if (jn > KCH) jn = KCH;
        {
            int j  = tid >> 1;
            int cb = (tid & 1) * 16;
            int row = kk + j;
            if (row < QN) {
                const float* kp = g_kp + ((size_t)(b*QN + row))*CDIM + h*HDIM + cb;
                const float* vp = g_vp + ((size_t)(b*QN + row))*CDIM + h*HDIM + cb;
                #pragma unroll
                for (int u = 0; u < 16; u += 4) {
                    *reinterpret_cast<float4*>(&Ks[j][cb + u]) =
                        *reinterpret_cast<const float4*>(kp + u);
                    *reinterpret_cast<float4*>(&Vs[j][cb + u]) =
                        *reinterpret_cast<const float4*>(vp + u);
                }
            } else {
                float4 zz = make_float4(0.f, 0.f, 0.f, 0.f);
                #pragma unroll
                for (int u = 0; u < 16; u += 4) {
                    *reinterpret_cast<float4*>(&Ks[j][cb + u]) = zz;
                    *reinterpret_cast<float4*>(&Vs[j][cb + u]) = zz;
                }
            }
        }
        __syncthreads();

        float s[KCH];
        #pragma unroll
        for (int j = 0; j < KCH; j++) s[j] = 0.f;
        #pragma unroll
        for (int d = 0; d < HDIM; d++) {
            float qd = qreg[d];
            #pragma unroll
            for (int j = 0; j < KCH; j++) s[j] += qd * Ks[j][d];
        }
        if (jn < KCH) {
            for (int j = jn; j < KCH; j++) s[j] = -1e30f;
        }
        float mnew = m;
        #pragma unroll
        for (int j = 0; j < KCH; j++) mnew = fmaxf(mnew, s[j]);
        float corr = __expf(m - mnew);
        l *= corr;
        #pragma unroll
        for (int d = 0; d < HDIM; d++) acc[d] *= corr;
        #pragma unroll
        for (int j = 0; j < KCH; j++) {
            float p = __expf(s[j] - mnew);
            l += p;
            #pragma unroll
            for (int d = 0; d < HDIM; d++) acc[d] += p * Vs[j][d];
        }
        m = mnew;
        __syncthreads();
    }

    if (active) {
        float invl = 1.f / l;
        float* o = g_o + ((size_t)(b*QN + qi))*CDIM + h*HDIM;
        #pragma unroll
        for (int d = 0; d < HDIM; d += 4) {
            float4 t;
            t.x = acc[d]   * invl; t.y = acc[d+1] * invl;
            t.z = acc[d+2] * invl; t.w = acc[d+3] * invl;
            *reinterpret_cast<float4*>(o + d) = t;
        }
    }
}

// ---------------------------------------------------------------------------
extern "C" void kernel_launch(void* const* d_in, const int* in_sizes, int n_in,
                              void* d_out, int out_size)
{
    const float* f0      = (const float*)d_in[0];
    const float* f1      = (const float*)d_in[1];
    const float* refs    = (const float*)d_in[2];
    const float* intr    = (const float*)d_in[3];
    const float* extr    = (const float*)d_in[4];
    const float* queries = (const float*)d_in[5];
    const float* Wq = (const float*)d_in[6];  const float* bq = (const float*)d_in[7];
    const float* Wk = (const float*)d_in[8];  const float* bk = (const float*)d_in[9];
    const float* Wv = (const float*)d_in[10]; const float* bv = (const float*)d_in[11];
    const float* Wo = (const float*)d_in[12]; const float* bo = (const float*)d_in[13];
    float* out = (float*)d_out;

    sampler_kernel<<<BQ, 256>>>(f0, f1, refs, intr, extr);
    gemm_qkv_kernel<<<dim3(29, 4, 3), 128>>>(queries, Wq, bq, Wk, bk, Wv, bv);
    attn_kernel<<<dim3(8, NHEADS, BATCH), 128>>>();
    gemm_out_kernel<<<dim3(29, 4, 1), 128>>>(Wo, bo, out);
}

// round 5
// speedup vs baseline: 1.1319x; 1.0012x over previous
#include <cuda_runtime.h>
#include <math.h>
#include <stdint.h>

#define BATCH   2
#define QN      900
#define BQ      (BATCH*QN)      // 1800
#define CDIM    256
#define VNUM    6
#define KKP     4
#define NSAMP   (VNUM*KKP)      // 24
#define NHEADS  8
#define HDIM    32

// scratch (no allocations allowed)
__device__ float g_ctx[BQ*CDIM];
__device__ float g_qp [BQ*CDIM];
__device__ float g_kp [BQ*CDIM];
__device__ float g_vp [BQ*CDIM];
__device__ float g_o  [BQ*CDIM];

// ---------------------------------------------------------------------------
// Kernel 1: project + bilinear-gather the multi-view context  -> g_ctx[B,Q,C]
// ---------------------------------------------------------------------------
__global__ __launch_bounds__(256) void sampler_kernel(
                               const float* __restrict__ f0,
                               const float* __restrict__ f1,
                               const float* __restrict__ refs,
                               const float* __restrict__ intr,
                               const float* __restrict__ extr)
{
    int bq = blockIdx.x;            // 0..1799
    int b  = bq / QN;
    int tid = threadIdx.x;

    __shared__ float s_w[2*NSAMP][4];
    __shared__ int   s_off[2*NSAMP][4];
    __shared__ int   s_valid[2*NSAMP];
    __shared__ int   s_cnt[2];
    __shared__ float s_ref[3];

    if (tid < 2) s_cnt[tid] = 0;
    if (tid < 3) s_ref[tid] = refs[(size_t)bq*3 + tid];
    __syncthreads();

    if (tid < 2*NSAMP) {
        int lvl = tid / NSAMP;
        int i   = tid % NSAMP;
        int v   = i / KKP, k = i % KKP;
        const float kx[4] = {0.f, 2.f, 0.f, -2.f};
        const float ky[4] = {0.f, 0.f, 2.f, 0.f};
        float rx = s_ref[0] + kx[k];
        float ry = s_ref[1] + ky[k];
        float rz = s_ref[2];
        const float* E  = extr + (size_t)(b*VNUM + v)*16;
        float cx = E[0]*rx + E[1]*ry + E[2]*rz  + E[3];
        float cy = E[4]*rx + E[5]*ry + E[6]*rz  + E[7];
        float cz = E[8]*rx + E[9]*ry + E[10]*rz + E[11];
        const float* Km = intr + (size_t)(b*VNUM + v)*9;
        float u  = Km[0]*cx + Km[1]*cy + Km[2]*cz;
        float vv = Km[3]*cx + Km[4]*cy + Km[5]*cz;
        float z  = Km[6]*cx + Km[7]*cy + Km[8]*cz;

        int W = lvl ? 88 : 176;
        int H = lvl ? 32 : 64;
        float zs = (fabsf(z) > 1e-6f) ? z : 1e-6f;
        float x = u / zs, y = vv / zs;   // grid-normalize cancels
        int valid = (z > 0.f) ? 1 : 0;
        s_valid[tid] = valid;
        if (valid) atomicAdd(&s_cnt[lvl], 1);

        float x0 = floorf(x), y0 = floorf(y);
        float wx1 = x - x0, wx0 = 1.f - wx1;
        float wy1 = y - y0, wy0 = 1.f - wy1;
        float xs[2]  = {x0, x0 + 1.f};
        float ys[2]  = {y0, y0 + 1.f};
        float wxs[2] = {wx0, wx1};
        float wys[2] = {wy0, wy1};
        #pragma unroll
        for (int t = 0; t < 4; t++) {
            float xi = xs[t & 1], yi = ys[t >> 1];
            bool inb = (xi >= 0.f) && (xi <= (float)(W - 1)) &&
                       (yi >= 0.f) && (yi <= (float)(H - 1));
            s_w[tid][t]   = wxs[t & 1] * wys[t >> 1];
            s_off[tid][t] = inb ? ((int)yi * W + (int)xi) : -1;
        }
    }
    __syncthreads();

    float invc0 = 1.f / fmaxf((float)s_cnt[0], 1.f);
    float invc1 = 1.f / fmaxf((float)s_cnt[1], 1.f);

    int c = tid;
    float total = 0.f;
    #pragma unroll
    for (int lvl = 0; lvl < 2; lvl++) {
        const float* f = lvl ? f1 : f0;
        int HW = lvl ? (32*88) : (64*176);
        float s = 0.f;
        for (int i = 0; i < NSAMP; i++) {
            int idx = lvl*NSAMP + i;
            if (!s_valid[idx]) continue;
            int v = i / KKP;
            size_t base = ((size_t)(b*VNUM + v)*CDIM + c) * (size_t)HW;
            #pragma unroll
            for (int t = 0; t < 4; t++) {
                int off = s_off[idx][t];
                if (off >= 0) s += s_w[idx][t] * __ldg(&f[base + off]);
            }
        }
        total += s * (lvl ? invc1 : invc0);
    }
    g_ctx[(size_t)bq*CDIM + c] = 0.5f * total;
}

// ---------------------------------------------------------------------------
// 3xTF32 tensor-core GEMM: C[M,256] = A[M,256] @ W^T + bias
// CTA tile 64x64, 4 warps (2x2), warp tile 32x32, BK=32, single-buffered.
// Accuracy: A,B split hi/lo tf32; D = Ah*Bh + Al*Bh + Ah*Bl  (~fp32 accurate)
// ---------------------------------------------------------------------------
__device__ __forceinline__ uint32_t f2tf32(float f) {
    uint32_t u;
    asm("cvt.rna.tf32.f32 %0, %1;" : "=r"(u) : "f"(f));
    return u;
}

__device__ __forceinline__ void mma_tf32(float* d, const uint32_t* a, const uint32_t* b) {
    asm volatile(
        "mma.sync.aligned.m16n8k8.row.col.f32.tf32.tf32.f32 "
        "{%0,%1,%2,%3}, {%4,%5,%6,%7}, {%8,%9}, {%0,%1,%2,%3};\n"
        : "+f"(d[0]), "+f"(d[1]), "+f"(d[2]), "+f"(d[3])
        : "r"(a[0]), "r"(a[1]), "r"(a[2]), "r"(a[3]), "r"(b[0]), "r"(b[1]));
}

#define KS 36   // smem k-stride (words): conflict-free fragment loads

__device__ __forceinline__ void tc_gemm_64x64(const float* __restrict__ A,
                                              const float* __restrict__ W,
                                              const float* __restrict__ bias,
                                              float* __restrict__ C,
                                              int M, int m0, int n0)
{
    __shared__ uint32_t Ah[64*KS], Al[64*KS], Bh[64*KS], Bl[64*KS];

    int tid  = threadIdx.x;
    int wid  = tid >> 5;
    int lane = tid & 31;
    int g  = lane >> 2;      // group id 0..7
    int tg = lane & 3;       // thread in group 0..3
    int wm = (wid & 1) * 32; // warp m offset
    int wn = (wid >> 1) * 32;// warp n offset

    // loader mapping: 64 rows x 32 cols per matrix, 128 threads x 16 floats
    int lr = tid >> 1;             // row 0..63
    int lc = (tid & 1) * 16;       // col base 0 or 16

    bool arv = (m0 + lr) < M;
    const float* arow = A + (size_t)(m0 + lr) * 256;
    const float* brow = W + (size_t)(n0 + lr) * 256;

    float acc[2][4][4];
    #pragma unroll
    for (int mt = 0; mt < 2; mt++)
        #pragma unroll
        for (int nt = 0; nt < 4; nt++)
            #pragma unroll
            for (int e = 0; e < 4; e++) acc[mt][nt][e] = 0.f;

    for (int k0 = 0; k0 < 256; k0 += 32) {
        // ---- stage tiles to smem with hi/lo tf32 split ----
        #pragma unroll
        for (int u = 0; u < 16; u += 4) {
            float4 va = arv ? *reinterpret_cast<const float4*>(arow + k0 + lc + u)
                            : make_float4(0.f, 0.f, 0.f, 0.f);
            float4 vb = *reinterpret_cast<const float4*>(brow + k0 + lc + u);
            float fa[4] = {va.x, va.y, va.z, va.w};
            float fb[4] = {vb.x, vb.y, vb.z, vb.w};
            #pragma unroll
            for (int e = 0; e < 4; e++) {
                uint32_t h = f2tf32(fa[e]);
                Ah[lr*KS + lc + u + e] = h;
                Al[lr*KS + lc + u + e] = f2tf32(fa[e] - __uint_as_float(h));
                h = f2tf32(fb[e]);
                Bh[lr*KS + lc + u + e] = h;
                Bl[lr*KS + lc + u + e] = f2tf32(fb[e] - __uint_as_float(h));
            }
        }
        __syncthreads();

        #pragma unroll
        for (int k8 = 0; k8 < 4; k8++) {
            int kb = k8 * 8;
            uint32_t ah[2][4], al[2][4], bh[4][2], bl[4][2];
            #pragma unroll
            for (int mt = 0; mt < 2; mt++) {
                int r0 = wm + mt*16 + g;
                ah[mt][0] = Ah[(r0    )*KS + kb + tg];
                ah[mt][1] = Ah[(r0 + 8)*KS + kb + tg];
                ah[mt][2] = Ah[(r0    )*KS + kb + tg + 4];
                ah[mt][3] = Ah[(r0 + 8)*KS + kb + tg + 4];
                al[mt][0] = Al[(r0    )*KS + kb + tg];
                al[mt][1] = Al[(r0 + 8)*KS + kb + tg];
                al[mt][2] = Al[(r0    )*KS + kb + tg + 4];
                al[mt][3] = Al[(r0 + 8)*KS + kb + tg + 4];
            }
            #pragma unroll
            for (int nt = 0; nt < 4; nt++) {
                int n = wn + nt*8 + g;
                bh[nt][0] = Bh[n*KS + kb + tg];
                bh[nt][1] = Bh[n*KS + kb + tg + 4];
                bl[nt][0] = Bl[n*KS + kb + tg];
                bl[nt][1] = Bl[n*KS + kb + tg + 4];
            }
            #pragma unroll
            for (int mt = 0; mt < 2; mt++)
                #pragma unroll
                for (int nt = 0; nt < 4; nt++) {
                    mma_tf32(acc[mt][nt], ah[mt], bh[nt]);
                    mma_tf32(acc[mt][nt], al[mt], bh[nt]);
                    mma_tf32(acc[mt][nt], ah[mt], bl[nt]);
                }
        }
        __syncthreads();
    }

    // ---- epilogue ----
    #pragma unroll
    for (int mt = 0; mt < 2; mt++) {
        #pragma unroll
        for (int nt = 0; nt < 4; nt++) {
            int rm = m0 + wm + mt*16 + g;
            int cn = n0 + wn + nt*8 + tg*2;
            float b0 = bias[cn], b1 = bias[cn + 1];
            if (rm < M) {
                C[(size_t)rm*256 + cn    ] = acc[mt][nt][0] + b0;
                C[(size_t)rm*256 + cn + 1] = acc[mt][nt][1] + b1;
            }
            if (rm + 8 < M) {
                C[(size_t)(rm+8)*256 + cn    ] = acc[mt][nt][2] + b0;
                C[(size_t)(rm+8)*256 + cn + 1] = acc[mt][nt][3] + b1;
            }
        }
    }
}

__global__ __launch_bounds__(128) void gemm_qkv_kernel(
                                const float* __restrict__ queries,
                                const float* __restrict__ Wq, const float* __restrict__ bq,
                                const float* __restrict__ Wk, const float* __restrict__ bk,
                                const float* __restrict__ Wv, const float* __restrict__ bv)
{
    const float* A; const float* W; const float* bias; float* C;
    if (blockIdx.z == 0)      { A = queries; W = Wq; bias = bq; C = g_qp; }
    else if (blockIdx.z == 1) { A = g_ctx;   W = Wk; bias = bk; C = g_kp; }
    else                      { A = g_ctx;   W = Wv; bias = bv; C = g_vp; }
    tc_gemm_64x64(A, W, bias, C, BQ, blockIdx.x*64, blockIdx.y*64);
}

__global__ __launch_bounds__(128) void gemm_out_kernel(
                                const float* __restrict__ Wo,
                                const float* __restrict__ bo,
                                float* __restrict__ out)
{
    tc_gemm_64x64(g_o, Wo, bo, out, BQ, blockIdx.x*64, blockIdx.y*64);
}

// ---------------------------------------------------------------------------
// Kernel 3: flash-style attention. 1 query/thread, 64-row K/V smem chunks.
// ---------------------------------------------------------------------------
#define KCH 64
__global__ __launch_bounds__(128) void attn_kernel()
{
    int qt = blockIdx.x, h = blockIdx.y, b = blockIdx.z;
    int tid = threadIdx.x;
    int qi = qt*128 + tid;
    bool active = qi < QN;

    __shared__ float Ks[KCH][32];
    __shared__ float Vs[KCH][32];

    const float scale = 0.17677669529663687f;  // 1/sqrt(32)
    float qreg[HDIM];
    if (active) {
        const float* qp = g_qp + ((size_t)(b*QN + qi))*CDIM + h*HDIM;
        #pragma unroll
        for (int d = 0; d < HDIM; d += 4) {
            float4 t = *reinterpret_cast<const float4*>(qp + d);
            qreg[d] = t.x*scale; qreg[d+1] = t.y*scale;
            qreg[d+2] = t.z*scale; qreg[d+3] = t.w*scale;
        }
    } else {
        #pragma unroll
        for (int d = 0; d < HDIM; d++) qreg[d] = 0.f;
    }

    float m = -1e30f, l = 0.f;
    float acc[HDIM];
    #pragma unroll
    for (int d = 0; d < HDIM; d++) acc[d] = 0.f;

    for (int kk = 0; kk < QN; kk += KCH) {
        int jn = QN - kk; if (jn > KCH) jn = KCH;
        {
            int j  = tid >> 1;
            int cb = (tid & 1) * 16;
            int row = kk + j;
            if (row < QN) {
                const float* kp = g_kp + ((size_t)(b*QN + row))*CDIM + h*HDIM + cb;
                const float* vp = g_vp + ((size_t)(b*QN + row))*CDIM + h*HDIM + cb;
                #pragma unroll
                for (int u = 0; u < 16; u += 4) {
                    *reinterpret_cast<float4*>(&Ks[j][cb + u]) =
                        *reinterpret_cast<const float4*>(kp + u);
                    *reinterpret_cast<float4*>(&Vs[j][cb + u]) =
                        *reinterpret_cast<const float4*>(vp + u);
                }
            } else {
                float4 zz = make_float4(0.f, 0.f, 0.f, 0.f);
                #pragma unroll
                for (int u = 0; u < 16; u += 4) {
                    *reinterpret_cast<float4*>(&Ks[j][cb + u]) = zz;
                    *reinterpret_cast<float4*>(&Vs[j][cb + u]) = zz;
                }
            }
        }
        __syncthreads();

        float s[KCH];
        #pragma unroll
        for (int j = 0; j < KCH; j++) s[j] = 0.f;
        #pragma unroll
        for (int d = 0; d < HDIM; d++) {
            float qd = qreg[d];
            #pragma unroll
            for (int j = 0; j < KCH; j++) s[j] += qd * Ks[j][d];
        }
        if (jn < KCH) {
            for (int j = jn; j < KCH; j++) s[j] = -1e30f;
        }
        float mnew = m;
        #pragma unroll
        for (int j = 0; j < KCH; j++) mnew = fmaxf(mnew, s[j]);
        float corr = __expf(m - mnew);
        l *= corr;
        #pragma unroll
        for (int d = 0; d < HDIM; d++) acc[d] *= corr;
        #pragma unroll
        for (int j = 0; j < KCH; j++) {
            float p = __expf(s[j] - mnew);
            l += p;
            #pragma unroll
            for (int d = 0; d < HDIM; d++) acc[d] += p * Vs[j][d];
        }
        m = mnew;
        __syncthreads();
    }

    if (active) {
        float invl = 1.f / l;
        float* o = g_o + ((size_t)(b*QN + qi))*CDIM + h*HDIM;
        #pragma unroll
        for (int d = 0; d < HDIM; d += 4) {
            float4 t;
            t.x = acc[d]   * invl; t.y = acc[d+1] * invl;
            t.z = acc[d+2] * invl; t.w = acc[d+3] * invl;
            *reinterpret_cast<float4*>(o + d) = t;
        }
    }
}

// ---------------------------------------------------------------------------
extern "C" void kernel_launch(void* const* d_in, const int* in_sizes, int n_in,
                              void* d_out, int out_size)
{
    const float* f0      = (const float*)d_in[0];
    const float* f1      = (const float*)d_in[1];
    const float* refs    = (const float*)d_in[2];
    const float* intr    = (const float*)d_in[3];
    const float* extr    = (const float*)d_in[4];
    const float* queries = (const float*)d_in[5];
    const float* Wq = (const float*)d_in[6];  const float* bq = (const float*)d_in[7];
    const float* Wk = (const float*)d_in[8];  const float* bk = (const float*)d_in[9];
    const float* Wv = (const float*)d_in[10]; const float* bv = (const float*)d_in[11];
    const float* Wo = (const float*)d_in[12]; const float* bo = (const float*)d_in[13];
    float* out = (float*)d_out;

    sampler_kernel<<<BQ, 256>>>(f0, f1, refs, intr, extr);
    gemm_qkv_kernel<<<dim3(29, 4, 3), 128>>>(queries, Wq, bq, Wk, bk, Wv, bv);
    attn_kernel<<<dim3(8, NHEADS, BATCH), 128>>>();
    gemm_out_kernel<<<dim3(29, 4, 1), 128>>>(Wo, bo, out);
}